// round 7
// baseline (speedup 1.0000x reference)
#include <cuda_runtime.h>
#include <cuda_bf16.h>
#include <math.h>
#include <stdint.h>

// ---------------- problem constants ----------------
#define BB 4
#define TT 2048
#define DD 1024
#define HH 8
#define DKk 128
#define DVv 256
#define CC 64
#define NCHUNK (TT / CC)   // 32
#define MROWS (BB * TT)    // 8192
#define NBH (BB * HH)      // 32

// ---------------- scratch (no runtime allocation allowed) ----------------
__device__ float g_q[MROWS * HH * DKk];
__device__ float g_k[MROWS * HH * DKk];
__device__ float g_v[MROWS * HH * DVv];
__device__ float g_g[MROWS * HH * DVv];
__device__ float g_o[MROWS * HH * DVv];

// retention intermediates
__device__ float g_attn[NBH * NCHUNK * CC * CC];          // 16.8M floats
__device__ float g_kv[NBH * NCHUNK * DKk * DVv];          // 33.5M floats
__device__ float g_S[NBH * NCHUNK * DKk * DVv];           // 33.5M floats

// bf16 split operands
__device__ __nv_bfloat16 g_xhi[MROWS * DD];
__device__ __nv_bfloat16 g_xlo[MROWS * DD];
__device__ __nv_bfloat16 g_ohi[MROWS * HH * DVv];
__device__ __nv_bfloat16 g_olo[MROWS * HH * DVv];
// transposed weights [N, K]
__device__ __nv_bfloat16 g_wq_hi[DD * DD],       g_wq_lo[DD * DD];
__device__ __nv_bfloat16 g_wk_hi[DD * DD],       g_wk_lo[DD * DD];
__device__ __nv_bfloat16 g_wv_hi[2 * DD * DD],   g_wv_lo[2 * DD * DD];
__device__ __nv_bfloat16 g_wg_hi[2 * DD * DD],   g_wg_lo[2 * DD * DD];
__device__ __nv_bfloat16 g_wo_hi[2 * DD * DD],   g_wo_lo[2 * DD * DD];

// ================= PTX helpers (plain sm_80+ ISA only) =================
__device__ __forceinline__ uint32_t smem_u32(const void* p) {
    uint32_t a;
    asm("{ .reg .u64 t; cvta.to.shared.u64 t, %1; cvt.u32.u64 %0, t; }" : "=r"(a) : "l"(p));
    return a;
}
#define CP_ASYNC16(dst, src) \
    asm volatile("cp.async.cg.shared.global [%0], [%1], 16;" :: "r"(dst), "l"(src))
#define CP_ASYNC_COMMIT() asm volatile("cp.async.commit_group;" ::: "memory")
#define CP_ASYNC_WAIT2() asm volatile("cp.async.wait_group 2;" ::: "memory")

__device__ __forceinline__ void ldsm4(uint32_t* r, uint32_t addr) {
    asm volatile("ldmatrix.sync.aligned.m8n8.x4.shared.b16 {%0,%1,%2,%3}, [%4];"
        : "=r"(r[0]), "=r"(r[1]), "=r"(r[2]), "=r"(r[3]) : "r"(addr));
}
__device__ __forceinline__ void mma16816(float* c, const uint32_t* a, const uint32_t* b) {
    asm volatile("mma.sync.aligned.m16n8k16.row.col.f32.bf16.bf16.f32 "
        "{%0,%1,%2,%3}, {%4,%5,%6,%7}, {%8,%9}, {%0,%1,%2,%3};"
        : "+f"(c[0]), "+f"(c[1]), "+f"(c[2]), "+f"(c[3])
        : "r"(a[0]), "r"(a[1]), "r"(a[2]), "r"(a[3]), "r"(b[0]), "r"(b[1]));
}

// ================= split-bf16 tensor-core GEMM (unchanged from R5) ==========
#define GSTAGES 3
#define GMAT_BYTES (128 * 64)
#define GSTAGE_BYTES (4 * GMAT_BYTES)
#define GEMM_SMEM_BYTES (GSTAGES * GSTAGE_BYTES)

__device__ __forceinline__ uint32_t swz(int row, int c16) {
    return (uint32_t)(row * 64 + ((c16 ^ ((row >> 1) & 3)) << 4));
}

__device__ __forceinline__ void load_tile32(uint32_t dst, const __nv_bfloat16* src,
                                            int row0, int k0, int ldk, int tid) {
    const char* gbase = (const char*)(src + (size_t)row0 * ldk + k0);
    const size_t rowb = (size_t)ldk * 2;
#pragma unroll
    for (int j = 0; j < 4; j++) {
        int e = tid + j * 128;
        int r = e >> 2, c16 = e & 3;
        CP_ASYNC16(dst + swz(r, c16), gbase + (size_t)r * rowb + c16 * 16);
    }
}

__global__ __launch_bounds__(128, 2) void gemm_split_mma(
    const __nv_bfloat16* __restrict__ Ahi, const __nv_bfloat16* __restrict__ Alo,
    const __nv_bfloat16* __restrict__ Bhi, const __nv_bfloat16* __restrict__ Blo,
    float* __restrict__ C, int M, int N, int K) {
    extern __shared__ char smem[];
    const uint32_t sb = smem_u32(smem);
    const int tid = threadIdx.x, lane = tid & 31, wid = tid >> 5;
    const int wm = wid & 1, wn = wid >> 1;
    const int m0 = blockIdx.y * 128, n0 = blockIdx.x * 128;
    const int nchunk = K >> 5;

    const int a_row = (lane & 7) + 8 * ((lane >> 3) & 1);
    const int a_c8  = lane >> 4;
    const int b_row = (lane & 7) + 8 * (lane >> 4);
    const int b_c8  = (lane >> 3) & 1;

    const int arow = wm * 64 + a_row;
    const int selA = (arow >> 1) & 3;
    const int brow = wn * 64 + b_row;
    const int selB = (brow >> 1) & 3;

    float acc[4][8][4];
#pragma unroll
    for (int i = 0; i < 4; i++)
#pragma unroll
        for (int j = 0; j < 8; j++)
#pragma unroll
            for (int r = 0; r < 4; r++) acc[i][j][r] = 0.f;

#pragma unroll
    for (int s = 0; s < GSTAGES; s++) {
        uint32_t st = sb + s * GSTAGE_BYTES;
        int k0 = s * 32;
        load_tile32(st,                  Ahi, m0, k0, K, tid);
        load_tile32(st + GMAT_BYTES,     Alo, m0, k0, K, tid);
        load_tile32(st + 2 * GMAT_BYTES, Bhi, n0, k0, K, tid);
        load_tile32(st + 3 * GMAT_BYTES, Blo, n0, k0, K, tid);
        CP_ASYNC_COMMIT();
    }

    for (int c = 0; c < nchunk; c++) {
        uint32_t st = sb + (c % GSTAGES) * GSTAGE_BYTES;
        CP_ASYNC_WAIT2();
        __syncthreads();

#pragma unroll
        for (int ks = 0; ks < 2; ks++) {
            const int ks2 = ks * 2;
            const uint32_t ca = (uint32_t)(((ks2 + a_c8) ^ selA) << 4);
            const uint32_t cb = (uint32_t)(((ks2 + b_c8) ^ selB) << 4);

            uint32_t ah[4][4], al[4][4];
#pragma unroll
            for (int mt = 0; mt < 4; mt++) {
                uint32_t ra = st + (uint32_t)((arow + mt * 16) * 64) + ca;
                ldsm4(ah[mt], ra);
                ldsm4(al[mt], ra + GMAT_BYTES);
            }
#pragma unroll
            for (int np = 0; np < 4; np++) {
                uint32_t bh[4], bl[4];
                uint32_t rb = st + 2 * GMAT_BYTES + (uint32_t)((brow + np * 16) * 64) + cb;
                ldsm4(bh, rb);
                ldsm4(bl, rb + GMAT_BYTES);
#pragma unroll
                for (int mt = 0; mt < 4; mt++)
#pragma unroll
                    for (int hf = 0; hf < 2; hf++) {
                        float* a4 = acc[mt][np * 2 + hf];
                        mma16816(a4, ah[mt], &bh[hf * 2]);
                        mma16816(a4, ah[mt], &bl[hf * 2]);
                        mma16816(a4, al[mt], &bh[hf * 2]);
                    }
            }
        }
        __syncthreads();

        if (c + GSTAGES < nchunk) {
            int k0 = (c + GSTAGES) * 32;
            load_tile32(st,                  Ahi, m0, k0, K, tid);
            load_tile32(st + GMAT_BYTES,     Alo, m0, k0, K, tid);
            load_tile32(st + 2 * GMAT_BYTES, Bhi, n0, k0, K, tid);
            load_tile32(st + 3 * GMAT_BYTES, Blo, n0, k0, K, tid);
        }
        CP_ASYNC_COMMIT();
    }

    const int crow = lane >> 2, ccol = (lane & 3) * 2;
#pragma unroll
    for (int mt = 0; mt < 4; mt++) {
        int rbase = m0 + wm * 64 + mt * 16 + crow;
#pragma unroll
        for (int nt = 0; nt < 8; nt++) {
            int cbase = n0 + wn * 64 + nt * 8 + ccol;
            float* d0 = C + (size_t)rbase * N + cbase;
            float* d1 = C + (size_t)(rbase + 8) * N + cbase;
            *(float2*)d0 = make_float2(acc[mt][nt][0], acc[mt][nt][1]);
            *(float2*)d1 = make_float2(acc[mt][nt][2], acc[mt][nt][3]);
        }
    }
}

// ================= split / transpose-split =================
__global__ __launch_bounds__(256) void split_kernel(const float* __restrict__ in,
                                                    __nv_bfloat16* __restrict__ hi,
                                                    __nv_bfloat16* __restrict__ lo, int n) {
    int i = blockIdx.x * blockDim.x + threadIdx.x;
    if (i >= n) return;
    float v = in[i];
    __nv_bfloat16 h = __float2bfloat16(v);
    hi[i] = h;
    lo[i] = __float2bfloat16(v - __bfloat162float(h));
}

__global__ __launch_bounds__(256) void tsplit_kernel(const float* __restrict__ W,
                                                     __nv_bfloat16* __restrict__ Thi,
                                                     __nv_bfloat16* __restrict__ Tlo,
                                                     int K, int N) {
    __shared__ float t[32][33];
    int n0 = blockIdx.x * 32, k0 = blockIdx.y * 32;
    int tx = threadIdx.x & 31, ty = threadIdx.x >> 5;
#pragma unroll
    for (int i = ty; i < 32; i += 8)
        t[i][tx] = W[(size_t)(k0 + i) * N + n0 + tx];
    __syncthreads();
#pragma unroll
    for (int i = ty; i < 32; i += 8) {
        float v = t[tx][i];
        __nv_bfloat16 h = __float2bfloat16(v);
        size_t oidx = (size_t)(n0 + i) * K + k0 + tx;
        Thi[oidx] = h;
        Tlo[oidx] = __float2bfloat16(v - __bfloat162float(h));
    }
}

// ---------------- RoPE (in place on q and k), q also scaled by DK^-1/2 ------
__global__ void rope_kernel(float* __restrict__ q, float* __restrict__ k) {
    int idx = blockIdx.x * blockDim.x + threadIdx.x;
    const int total = BB * TT * HH * (DKk / 2);
    if (idx >= total) return;
    int i = idx & 63;
    int h = (idx >> 6) & (HH - 1);
    int t = (idx >> 9) & (TT - 1);
    int b = idx >> 20;

    float inv = powf(10000.f, -(float)i * (1.0f / 64.0f));
    float f = (float)t * inv;
    float s, c;
    sincosf(f, &s, &c);

    size_t base = ((((size_t)b * TT + t) * HH + h) << 7);
    const float sc = 0.08838834764831845f;
    float q1 = q[base + i], q2 = q[base + 64 + i];
    q[base + i]      = (q1 * c - q2 * s) * sc;
    q[base + 64 + i] = (q2 * c + q1 * s) * sc;
    float k1 = k[base + i], k2 = k[base + 64 + i];
    k[base + i]      = k1 * c - k2 * s;
    k[base + 64 + i] = k2 * c + k1 * s;
}

// ================= retention, 4 parallel phases =================

// Phase A: attn[b,h,n] = (q_chunk @ k_chunk^T) * M   -> g_attn
// grid (NCHUNK, HH, BB), 256 threads
#define ATTN_SMEM ((2 * 64 * 129 + 64) * 4)
__global__ __launch_bounds__(256) void ret_attn_kernel(const float* __restrict__ q,
                                                       const float* __restrict__ k,
                                                       float* __restrict__ attn_out) {
    const int n = blockIdx.x, h = blockIdx.y, b = blockIdx.z;
    const int tid = threadIdx.x;
    extern __shared__ float sm[];
    float* qs   = sm;              // 64*129
    float* ks   = qs + 64 * 129;   // 64*129
    float* gpow = ks + 64 * 129;   // 64

    const float gamma = 1.0f - exp2f(-5.0f - (float)h);
    if (tid < 64) gpow[tid] = powf(gamma, (float)tid);

    const int t0 = n * CC;
    for (int e = tid; e < 64 * 128; e += 256) {
        int i = e >> 7, dk = e & 127;
        size_t gi = ((((size_t)b * TT + t0 + i) * HH + h) << 7) + dk;
        qs[i * 129 + dk] = q[gi];
        ks[i * 129 + dk] = k[gi];
    }
    __syncthreads();

    const int ti = tid >> 4, te = tid & 15;
    float acc[4][4];
#pragma unroll
    for (int a = 0; a < 4; a++)
#pragma unroll
        for (int bq = 0; bq < 4; bq++) acc[a][bq] = 0.f;
    for (int dk = 0; dk < 128; dk++) {
        float ra[4], rb[4];
#pragma unroll
        for (int ii = 0; ii < 4; ii++) ra[ii] = qs[(ti * 4 + ii) * 129 + dk];
#pragma unroll
        for (int jj = 0; jj < 4; jj++) rb[jj] = ks[(te * 4 + jj) * 129 + dk];
#pragma unroll
        for (int ii = 0; ii < 4; ii++)
#pragma unroll
            for (int jj = 0; jj < 4; jj++) acc[ii][jj] += ra[ii] * rb[jj];
    }

    float* dst = attn_out + ((((size_t)b * HH + h) * NCHUNK + n) << 12);
#pragma unroll
    for (int ii = 0; ii < 4; ii++) {
        int i = ti * 4 + ii;
        float4 w;
        float* wp = &w.x;
#pragma unroll
        for (int jj = 0; jj < 4; jj++) {
            int j = te * 4 + jj;
            wp[jj] = (i >= j) ? acc[ii][jj] * gpow[i - j] : 0.f;
        }
        *(float4*)(dst + i * 64 + te * 4) = w;
    }
}

// Phase B: kv[b,h,n] = (k*deck)^T @ v   -> g_kv   (per DV slice of 64)
// grid (4*NCHUNK, HH, BB), 256 threads
#define KV_SMEM ((64 * 129 + 64 * 65 + 64) * 4)
__global__ __launch_bounds__(256) void ret_kv_kernel(const float* __restrict__ k,
                                                     const float* __restrict__ v,
                                                     float* __restrict__ kv_out) {
    const int sl = blockIdx.x & 3, n = blockIdx.x >> 2;
    const int h = blockIdx.y, b = blockIdx.z;
    const int tid = threadIdx.x;
    extern __shared__ float sm[];
    float* ks   = sm;              // 64*129
    float* vs   = ks + 64 * 129;   // 64*65  (pre-scaled by deck)
    float* deck = vs + 64 * 65;    // 64

    const float gamma = 1.0f - exp2f(-5.0f - (float)h);
    if (tid < 64) deck[tid] = powf(gamma, (float)(63 - tid));
    __syncthreads();

    const int t0 = n * CC;
    for (int e = tid; e < 64 * 128; e += 256) {
        int i = e >> 7, dk = e & 127;
        size_t gi = ((((size_t)b * TT + t0 + i) * HH + h) << 7) + dk;
        ks[i * 129 + dk] = k[gi];
    }
    for (int e = tid; e < 64 * 64; e += 256) {
        int i = e >> 6, ev = e & 63;
        size_t gi = (((size_t)b * TT + t0 + i) * HH + h) * DVv + sl * 64 + ev;
        vs[i * 65 + ev] = v[gi] * deck[i];
    }
    __syncthreads();

    const int ti = tid >> 4, te = tid & 15;   // dk group of 8, ev group of 4
    float acc[8][4];
#pragma unroll
    for (int a = 0; a < 8; a++)
#pragma unroll
        for (int bq = 0; bq < 4; bq++) acc[a][bq] = 0.f;
    for (int j = 0; j < 64; j++) {
        float ra[8], rb[4];
#pragma unroll
        for (int dd = 0; dd < 8; dd++) ra[dd] = ks[j * 129 + ti * 8 + dd];
#pragma unroll
        for (int ee = 0; ee < 4; ee++) rb[ee] = vs[j * 65 + te * 4 + ee];
#pragma unroll
        for (int dd = 0; dd < 8; dd++)
#pragma unroll
            for (int ee = 0; ee < 4; ee++) acc[dd][ee] += ra[dd] * rb[ee];
    }

    float* dst = kv_out + ((((size_t)b * HH + h) * NCHUNK + n) * DKk) * DVv + sl * 64;
#pragma unroll
    for (int dd = 0; dd < 8; dd++) {
        int dk = ti * 8 + dd;
        *(float4*)(dst + (size_t)dk * DVv + te * 4) =
            make_float4(acc[dd][0], acc[dd][1], acc[dd][2], acc[dd][3]);
    }
}

// Phase C: S_pre[n] = gC*S_pre[n-1] + kv[n-1], S_pre[0] = 0  -> g_S
// one thread per (bh, dk, ev); grid 4096 x 256
__global__ __launch_bounds__(256) void ret_scan_kernel(const float* __restrict__ kv,
                                                       float* __restrict__ Spre) {
    const int idx = blockIdx.x * 256 + threadIdx.x;   // < 32*128*256
    const int bh  = idx >> 15;
    const int pos = idx & 32767;
    const int h   = bh & (HH - 1);
    const float gamma = 1.0f - exp2f(-5.0f - (float)h);
    const float gC = powf(gamma, 64.0f);

    const size_t base = (size_t)bh * NCHUNK * 32768 + pos;
    float s = 0.f;
    Spre[base] = 0.f;
    for (int n = 1; n < NCHUNK; n++) {
        s = gC * s + kv[base + (size_t)(n - 1) * 32768];
        Spre[base + (size_t)n * 32768] = s;
    }
}

// Phase D: o = attn @ v + decq * (q @ S_pre)   (per DV slice of 64)
// grid (4*NCHUNK, HH, BB), 256 threads
#define OUT_SMEM ((64 * 65 + 64 * 65 + 64 * 129 + 128 * 65 + 64) * 4)
__global__ __launch_bounds__(256) void ret_out_kernel(const float* __restrict__ q,
                                                      const float* __restrict__ v,
                                                      const float* __restrict__ attn,
                                                      const float* __restrict__ Spre,
                                                      float* __restrict__ o) {
    const int sl = blockIdx.x & 3, n = blockIdx.x >> 2;
    const int h = blockIdx.y, b = blockIdx.z;
    const int tid = threadIdx.x;
    extern __shared__ float sm[];
    float* at   = sm;               // 64*65
    float* vs   = at + 64 * 65;     // 64*65
    float* qs   = vs + 64 * 65;     // 64*129
    float* Ss   = qs + 64 * 129;    // 128*65
    float* decq = Ss + 128 * 65;    // 64

    const float gamma = 1.0f - exp2f(-5.0f - (float)h);
    if (tid < 64) decq[tid] = powf(gamma, (float)(tid + 1));

    const int t0 = n * CC;
    const size_t bh = (size_t)b * HH + h;
    const float* asrc = attn + ((bh * NCHUNK + n) << 12);
    for (int e = tid; e < 64 * 64; e += 256) {
        int i = e >> 6, j = e & 63;
        at[i * 65 + j] = asrc[e];
        size_t gi = (((size_t)b * TT + t0 + i) * HH + h) * DVv + sl * 64 + j;
        vs[i * 65 + j] = v[gi];
    }
    for (int e = tid; e < 64 * 128; e += 256) {
        int i = e >> 7, dk = e & 127;
        size_t gi = ((((size_t)b * TT + t0 + i) * HH + h) << 7) + dk;
        qs[i * 129 + dk] = q[gi];
    }
    const float* ssrc = Spre + ((bh * NCHUNK + n) * DKk) * DVv + sl * 64;
    for (int e = tid; e < 128 * 64; e += 256) {
        int dk = e >> 6, ev = e & 63;
        Ss[dk * 65 + ev] = ssrc[(size_t)dk * DVv + ev];
    }
    __syncthreads();

    const int ti = tid >> 4, te = tid & 15;
    float aI[4][4], aS[4][4];
#pragma unroll
    for (int a = 0; a < 4; a++)
#pragma unroll
        for (int bq = 0; bq < 4; bq++) { aI[a][bq] = 0.f; aS[a][bq] = 0.f; }

    for (int j = 0; j < 64; j++) {
        float ra[4], rb[4];
#pragma unroll
        for (int ii = 0; ii < 4; ii++) ra[ii] = at[(ti * 4 + ii) * 65 + j];
#pragma unroll
        for (int ee = 0; ee < 4; ee++) rb[ee] = vs[j * 65 + te * 4 + ee];
#pragma unroll
        for (int ii = 0; ii < 4; ii++)
#pragma unroll
            for (int ee = 0; ee < 4; ee++) aI[ii][ee] += ra[ii] * rb[ee];
    }
    for (int dk = 0; dk < 128; dk++) {
        float ra[4], rb[4];
#pragma unroll
        for (int ii = 0; ii < 4; ii++) ra[ii] = qs[(ti * 4 + ii) * 129 + dk];
#pragma unroll
        for (int ee = 0; ee < 4; ee++) rb[ee] = Ss[dk * 65 + te * 4 + ee];
#pragma unroll
        for (int ii = 0; ii < 4; ii++)
#pragma unroll
            for (int ee = 0; ee < 4; ee++) aS[ii][ee] += ra[ii] * rb[ee];
    }

#pragma unroll
    for (int ii = 0; ii < 4; ii++) {
        int i = ti * 4 + ii;
        float dq = decq[i];
        size_t base = (((size_t)b * TT + t0 + i) * HH + h) * DVv + sl * 64 + te * 4;
        *(float4*)(&o[base]) = make_float4(aI[ii][0] + dq * aS[ii][0],
                                           aI[ii][1] + dq * aS[ii][1],
                                           aI[ii][2] + dq * aS[ii][2],
                                           aI[ii][3] + dq * aS[ii][3]);
    }
}

// ---------------- RMSNorm + swish gate + bf16 split (fused) ----------------
__global__ __launch_bounds__(256) void normgate_split_kernel(const float* __restrict__ o,
                                                             const float* __restrict__ g,
                                                             const float* __restrict__ norm_w,
                                                             __nv_bfloat16* __restrict__ ohi,
                                                             __nv_bfloat16* __restrict__ olo) {
    int warp = (blockIdx.x * blockDim.x + threadIdx.x) >> 5;
    int lane = threadIdx.x & 31;
    if (warp >= MROWS * HH) return;
    size_t base = (size_t)warp * DVv;

    float vals[8];
    float ss = 0.f;
#pragma unroll
    for (int r = 0; r < 8; r++) {
        vals[r] = o[base + lane + 32 * r];
        ss += vals[r] * vals[r];
    }
#pragma unroll
    for (int off = 16; off; off >>= 1) ss += __shfl_xor_sync(0xFFFFFFFFu, ss, off);
    float inv = rsqrtf(ss * (1.0f / 256.0f) + 1e-5f);

#pragma unroll
    for (int r = 0; r < 8; r++) {
        int ev = lane + 32 * r;
        float gv = g[base + ev];
        float sg = 1.f / (1.f + expf(-gv));
        float res = vals[r] * inv * norm_w[ev] * gv * sg;
        __nv_bfloat16 h = __float2bfloat16(res);
        ohi[base + ev] = h;
        olo[base + ev] = __float2bfloat16(res - __bfloat162float(h));
    }
}

// ---------------- launch ----------------
static void launch_gemm(const __nv_bfloat16* Ahi, const __nv_bfloat16* Alo,
                        const __nv_bfloat16* Bhi, const __nv_bfloat16* Blo,
                        float* C, int M, int N, int K) {
    gemm_split_mma<<<dim3(N / 128, M / 128), 128, GEMM_SMEM_BYTES>>>(Ahi, Alo, Bhi, Blo, C, M, N, K);
}

extern "C" void kernel_launch(void* const* d_in, const int* in_sizes, int n_in,
                              void* d_out, int out_size) {
    const float* x      = (const float*)d_in[0];
    const float* Wq     = (const float*)d_in[1];
    const float* Wk     = (const float*)d_in[2];
    const float* Wv     = (const float*)d_in[3];
    const float* Wg     = (const float*)d_in[4];
    const float* Wo     = (const float*)d_in[5];
    const float* norm_w = (const float*)d_in[6];
    float* out = (float*)d_out;

    float *q, *k, *v, *g, *o, *attn, *kv, *S;
    cudaGetSymbolAddress((void**)&q, g_q);
    cudaGetSymbolAddress((void**)&k, g_k);
    cudaGetSymbolAddress((void**)&v, g_v);
    cudaGetSymbolAddress((void**)&g, g_g);
    cudaGetSymbolAddress((void**)&o, g_o);
    cudaGetSymbolAddress((void**)&attn, g_attn);
    cudaGetSymbolAddress((void**)&kv, g_kv);
    cudaGetSymbolAddress((void**)&S, g_S);
    __nv_bfloat16 *xhi, *xlo, *ohi, *olo;
    __nv_bfloat16 *wqh, *wql, *wkh, *wkl, *wvh, *wvl, *wgh, *wgl, *woh, *wol;
    cudaGetSymbolAddress((void**)&xhi, g_xhi);
    cudaGetSymbolAddress((void**)&xlo, g_xlo);
    cudaGetSymbolAddress((void**)&ohi, g_ohi);
    cudaGetSymbolAddress((void**)&olo, g_olo);
    cudaGetSymbolAddress((void**)&wqh, g_wq_hi); cudaGetSymbolAddress((void**)&wql, g_wq_lo);
    cudaGetSymbolAddress((void**)&wkh, g_wk_hi); cudaGetSymbolAddress((void**)&wkl, g_wk_lo);
    cudaGetSymbolAddress((void**)&wvh, g_wv_hi); cudaGetSymbolAddress((void**)&wvl, g_wv_lo);
    cudaGetSymbolAddress((void**)&wgh, g_wg_hi); cudaGetSymbolAddress((void**)&wgl, g_wg_lo);
    cudaGetSymbolAddress((void**)&woh, g_wo_hi); cudaGetSymbolAddress((void**)&wol, g_wo_lo);

    cudaFuncSetAttribute(gemm_split_mma, cudaFuncAttributeMaxDynamicSharedMemorySize, GEMM_SMEM_BYTES);
    cudaFuncSetAttribute(ret_attn_kernel, cudaFuncAttributeMaxDynamicSharedMemorySize, ATTN_SMEM);
    cudaFuncSetAttribute(ret_kv_kernel, cudaFuncAttributeMaxDynamicSharedMemorySize, KV_SMEM);
    cudaFuncSetAttribute(ret_out_kernel, cudaFuncAttributeMaxDynamicSharedMemorySize, OUT_SMEM);

    // split inputs + transpose-split weights
    {
        int n = MROWS * DD;
        split_kernel<<<(n + 255) / 256, 256>>>(x, xhi, xlo, n);
    }
    tsplit_kernel<<<dim3(DD / 32, DD / 32), 256>>>(Wq, wqh, wql, DD, DD);
    tsplit_kernel<<<dim3(DD / 32, DD / 32), 256>>>(Wk, wkh, wkl, DD, DD);
    tsplit_kernel<<<dim3(2 * DD / 32, DD / 32), 256>>>(Wv, wvh, wvl, DD, 2 * DD);
    tsplit_kernel<<<dim3(2 * DD / 32, DD / 32), 256>>>(Wg, wgh, wgl, DD, 2 * DD);
    tsplit_kernel<<<dim3(DD / 32, 2 * DD / 32), 256>>>(Wo, woh, wol, 2 * DD, DD);

    // projections on tensor cores
    launch_gemm(xhi, xlo, wqh, wql, q, MROWS, DD, DD);
    launch_gemm(xhi, xlo, wkh, wkl, k, MROWS, DD, DD);
    launch_gemm(xhi, xlo, wvh, wvl, v, MROWS, 2 * DD, DD);
    launch_gemm(xhi, xlo, wgh, wgl, g, MROWS, 2 * DD, DD);

    // rope + scale
    {
        int total = BB * TT * HH * (DKk / 2);
        rope_kernel<<<(total + 255) / 256, 256>>>(q, k);
    }

    // retention: 4 parallel phases
    ret_attn_kernel<<<dim3(NCHUNK, HH, BB), 256, ATTN_SMEM>>>(q, k, attn);
    ret_kv_kernel<<<dim3(4 * NCHUNK, HH, BB), 256, KV_SMEM>>>(k, v, kv);
    ret_scan_kernel<<<(NBH * DKk * DVv) / 256, 256>>>(kv, S);
    ret_out_kernel<<<dim3(4 * NCHUNK, HH, BB), 256, OUT_SMEM>>>(q, v, attn, S, o);

    // rmsnorm + gate + split (fused)
    {
        int warps = MROWS * HH;
        normgate_split_kernel<<<(warps * 32 + 255) / 256, 256>>>(o, g, norm_w, ohi, olo);
    }

    // output projection on tensor cores
    launch_gemm(ohi, olo, woh, wol, out, MROWS, DD, 2 * DD);
}

// round 8
// speedup vs baseline: 1.0249x; 1.0249x over previous
#include <cuda_runtime.h>
#include <cuda_bf16.h>
#include <math.h>
#include <stdint.h>

// ---------------- problem constants ----------------
#define BB 4
#define TT 2048
#define DD 1024
#define HH 8
#define DKk 128
#define DVv 256
#define CC 64
#define NCHUNK (TT / CC)   // 32
#define MROWS (BB * TT)    // 8192
#define NBH (BB * HH)      // 32
#define NQKVG 6144         // q(1024) | k(1024) | v(2048) | g(2048)

// ---------------- scratch (no runtime allocation allowed) ----------------
__device__ float g_qkvg[MROWS * NQKVG];    // combined projection output (201MB)
__device__ float g_o[MROWS * HH * DVv];

// retention intermediates
__device__ float g_attn[NBH * NCHUNK * CC * CC];
__device__ float g_kv[NBH * NCHUNK * DKk * DVv];
__device__ float g_S[NBH * NCHUNK * DKk * DVv];

// bf16 split operands
__device__ __nv_bfloat16 g_xhi[MROWS * DD];
__device__ __nv_bfloat16 g_xlo[MROWS * DD];
__device__ __nv_bfloat16 g_ohi[MROWS * HH * DVv];
__device__ __nv_bfloat16 g_olo[MROWS * HH * DVv];
// transposed weights [N, K]
__device__ __nv_bfloat16 g_wall_hi[NQKVG * DD], g_wall_lo[NQKVG * DD];
__device__ __nv_bfloat16 g_wo_hi[2 * DD * DD],  g_wo_lo[2 * DD * DD];

// ================= PTX helpers (plain sm_80+ ISA only) =================
__device__ __forceinline__ uint32_t smem_u32(const void* p) {
    uint32_t a;
    asm("{ .reg .u64 t; cvta.to.shared.u64 t, %1; cvt.u32.u64 %0, t; }" : "=r"(a) : "l"(p));
    return a;
}
#define CP_ASYNC16(dst, src) \
    asm volatile("cp.async.cg.shared.global [%0], [%1], 16;" :: "r"(dst), "l"(src))
#define CP_ASYNC_COMMIT() asm volatile("cp.async.commit_group;" ::: "memory")
#define CP_ASYNC_WAIT2() asm volatile("cp.async.wait_group 2;" ::: "memory")

__device__ __forceinline__ void ldsm4(uint32_t* r, uint32_t addr) {
    asm volatile("ldmatrix.sync.aligned.m8n8.x4.shared.b16 {%0,%1,%2,%3}, [%4];"
        : "=r"(r[0]), "=r"(r[1]), "=r"(r[2]), "=r"(r[3]) : "r"(addr));
}
__device__ __forceinline__ void mma16816(float* c, const uint32_t* a, const uint32_t* b) {
    asm volatile("mma.sync.aligned.m16n8k16.row.col.f32.bf16.bf16.f32 "
        "{%0,%1,%2,%3}, {%4,%5,%6,%7}, {%8,%9}, {%0,%1,%2,%3};"
        : "+f"(c[0]), "+f"(c[1]), "+f"(c[2]), "+f"(c[3])
        : "r"(a[0]), "r"(a[1]), "r"(a[2]), "r"(a[3]), "r"(b[0]), "r"(b[1]));
}

// ================= split-bf16 tensor-core GEMM =================
#define GSTAGES 3
#define GMAT_BYTES (128 * 64)
#define GSTAGE_BYTES (4 * GMAT_BYTES)
#define GEMM_SMEM_BYTES (GSTAGES * GSTAGE_BYTES)

__device__ __forceinline__ uint32_t swz(int row, int c16) {
    return (uint32_t)(row * 64 + ((c16 ^ ((row >> 1) & 3)) << 4));
}

__device__ __forceinline__ void load_tile32(uint32_t dst, const __nv_bfloat16* src,
                                            int row0, int k0, int ldk, int tid) {
    const char* gbase = (const char*)(src + (size_t)row0 * ldk + k0);
    const size_t rowb = (size_t)ldk * 2;
#pragma unroll
    for (int j = 0; j < 4; j++) {
        int e = tid + j * 128;
        int r = e >> 2, c16 = e & 3;
        CP_ASYNC16(dst + swz(r, c16), gbase + (size_t)r * rowb + c16 * 16);
    }
}

__global__ __launch_bounds__(128, 2) void gemm_split_mma(
    const __nv_bfloat16* __restrict__ Ahi, const __nv_bfloat16* __restrict__ Alo,
    const __nv_bfloat16* __restrict__ Bhi, const __nv_bfloat16* __restrict__ Blo,
    float* __restrict__ C, int M, int N, int K) {
    extern __shared__ char smem[];
    const uint32_t sb = smem_u32(smem);
    const int tid = threadIdx.x, lane = tid & 31, wid = tid >> 5;
    const int wm = wid & 1, wn = wid >> 1;
    const int m0 = blockIdx.y * 128, n0 = blockIdx.x * 128;
    const int nchunk = K >> 5;

    const int a_row = (lane & 7) + 8 * ((lane >> 3) & 1);
    const int a_c8  = lane >> 4;
    const int b_row = (lane & 7) + 8 * (lane >> 4);
    const int b_c8  = (lane >> 3) & 1;

    const int arow = wm * 64 + a_row;
    const int selA = (arow >> 1) & 3;
    const int brow = wn * 64 + b_row;
    const int selB = (brow >> 1) & 3;

    float acc[4][8][4];
#pragma unroll
    for (int i = 0; i < 4; i++)
#pragma unroll
        for (int j = 0; j < 8; j++)
#pragma unroll
            for (int r = 0; r < 4; r++) acc[i][j][r] = 0.f;

#pragma unroll
    for (int s = 0; s < GSTAGES; s++) {
        uint32_t st = sb + s * GSTAGE_BYTES;
        int k0 = s * 32;
        load_tile32(st,                  Ahi, m0, k0, K, tid);
        load_tile32(st + GMAT_BYTES,     Alo, m0, k0, K, tid);
        load_tile32(st + 2 * GMAT_BYTES, Bhi, n0, k0, K, tid);
        load_tile32(st + 3 * GMAT_BYTES, Blo, n0, k0, K, tid);
        CP_ASYNC_COMMIT();
    }

    for (int c = 0; c < nchunk; c++) {
        uint32_t st = sb + (c % GSTAGES) * GSTAGE_BYTES;
        CP_ASYNC_WAIT2();
        __syncthreads();

#pragma unroll
        for (int ks = 0; ks < 2; ks++) {
            const int ks2 = ks * 2;
            const uint32_t ca = (uint32_t)(((ks2 + a_c8) ^ selA) << 4);
            const uint32_t cb = (uint32_t)(((ks2 + b_c8) ^ selB) << 4);

            uint32_t ah[4][4], al[4][4];
#pragma unroll
            for (int mt = 0; mt < 4; mt++) {
                uint32_t ra = st + (uint32_t)((arow + mt * 16) * 64) + ca;
                ldsm4(ah[mt], ra);
                ldsm4(al[mt], ra + GMAT_BYTES);
            }
#pragma unroll
            for (int np = 0; np < 4; np++) {
                uint32_t bh[4], bl[4];
                uint32_t rb = st + 2 * GMAT_BYTES + (uint32_t)((brow + np * 16) * 64) + cb;
                ldsm4(bh, rb);
                ldsm4(bl, rb + GMAT_BYTES);
#pragma unroll
                for (int mt = 0; mt < 4; mt++)
#pragma unroll
                    for (int hf = 0; hf < 2; hf++) {
                        float* a4 = acc[mt][np * 2 + hf];
                        mma16816(a4, ah[mt], &bh[hf * 2]);
                        mma16816(a4, ah[mt], &bl[hf * 2]);
                        mma16816(a4, al[mt], &bh[hf * 2]);
                    }
            }
        }
        __syncthreads();

        if (c + GSTAGES < nchunk) {
            int k0 = (c + GSTAGES) * 32;
            load_tile32(st,                  Ahi, m0, k0, K, tid);
            load_tile32(st + GMAT_BYTES,     Alo, m0, k0, K, tid);
            load_tile32(st + 2 * GMAT_BYTES, Bhi, n0, k0, K, tid);
            load_tile32(st + 3 * GMAT_BYTES, Blo, n0, k0, K, tid);
        }
        CP_ASYNC_COMMIT();
    }

    const int crow = lane >> 2, ccol = (lane & 3) * 2;
#pragma unroll
    for (int mt = 0; mt < 4; mt++) {
        int rbase = m0 + wm * 64 + mt * 16 + crow;
#pragma unroll
        for (int nt = 0; nt < 8; nt++) {
            int cbase = n0 + wn * 64 + nt * 8 + ccol;
            float* d0 = C + (size_t)rbase * N + cbase;
            float* d1 = C + (size_t)(rbase + 8) * N + cbase;
            *(float2*)d0 = make_float2(acc[mt][nt][0], acc[mt][nt][1]);
            *(float2*)d1 = make_float2(acc[mt][nt][2], acc[mt][nt][3]);
        }
    }
}

// ================= split / transpose-split =================
__global__ __launch_bounds__(256) void split_kernel(const float* __restrict__ in,
                                                    __nv_bfloat16* __restrict__ hi,
                                                    __nv_bfloat16* __restrict__ lo, int n) {
    int i = blockIdx.x * blockDim.x + threadIdx.x;
    if (i >= n) return;
    float v = in[i];
    __nv_bfloat16 h = __float2bfloat16(v);
    hi[i] = h;
    lo[i] = __float2bfloat16(v - __bfloat162float(h));
}

// combined transpose-split for Wq|Wk|Wv|Wg (all K=1024) into g_wall [6144,1024]
__global__ __launch_bounds__(256) void tsplit_qkvg_kernel(const float* __restrict__ Wq,
                                                          const float* __restrict__ Wk,
                                                          const float* __restrict__ Wv,
                                                          const float* __restrict__ Wg,
                                                          __nv_bfloat16* __restrict__ Thi,
                                                          __nv_bfloat16* __restrict__ Tlo) {
    __shared__ float t[32][33];
    int n0 = blockIdx.x * 32, k0 = blockIdx.y * 32;
    const float* W;
    int srcN, ln0;
    if (n0 < 1024)       { W = Wq; srcN = 1024; ln0 = n0; }
    else if (n0 < 2048)  { W = Wk; srcN = 1024; ln0 = n0 - 1024; }
    else if (n0 < 4096)  { W = Wv; srcN = 2048; ln0 = n0 - 2048; }
    else                 { W = Wg; srcN = 2048; ln0 = n0 - 4096; }

    int tx = threadIdx.x & 31, ty = threadIdx.x >> 5;
#pragma unroll
    for (int i = ty; i < 32; i += 8)
        t[i][tx] = W[(size_t)(k0 + i) * srcN + ln0 + tx];
    __syncthreads();
#pragma unroll
    for (int i = ty; i < 32; i += 8) {
        float v = t[tx][i];
        __nv_bfloat16 h = __float2bfloat16(v);
        size_t oidx = (size_t)(n0 + i) * DD + k0 + tx;
        Thi[oidx] = h;
        Tlo[oidx] = __float2bfloat16(v - __bfloat162float(h));
    }
}

// W: [K, N] fp32 -> Thi/Tlo: [N, K] bf16 (for Wo)
__global__ __launch_bounds__(256) void tsplit_kernel(const float* __restrict__ W,
                                                     __nv_bfloat16* __restrict__ Thi,
                                                     __nv_bfloat16* __restrict__ Tlo,
                                                     int K, int N) {
    __shared__ float t[32][33];
    int n0 = blockIdx.x * 32, k0 = blockIdx.y * 32;
    int tx = threadIdx.x & 31, ty = threadIdx.x >> 5;
#pragma unroll
    for (int i = ty; i < 32; i += 8)
        t[i][tx] = W[(size_t)(k0 + i) * N + n0 + tx];
    __syncthreads();
#pragma unroll
    for (int i = ty; i < 32; i += 8) {
        float v = t[tx][i];
        __nv_bfloat16 h = __float2bfloat16(v);
        size_t oidx = (size_t)(n0 + i) * K + k0 + tx;
        Thi[oidx] = h;
        Tlo[oidx] = __float2bfloat16(v - __bfloat162float(h));
    }
}

// ---------------- RoPE on the combined buffer (q: cols 0-1023, k: 1024-2047) --
__global__ void rope_kernel(float* __restrict__ qkvg) {
    int idx = blockIdx.x * blockDim.x + threadIdx.x;
    const int total = BB * TT * HH * (DKk / 2);
    if (idx >= total) return;
    int i = idx & 63;
    int h = (idx >> 6) & (HH - 1);
    int t = (idx >> 9) & (TT - 1);
    int b = idx >> 20;

    float inv = powf(10000.f, -(float)i * (1.0f / 64.0f));
    float f = (float)t * inv;
    float s, c;
    sincosf(f, &s, &c);

    size_t base = ((size_t)b * TT + t) * NQKVG + h * DKk;
    const float sc = 0.08838834764831845f;
    float q1 = qkvg[base + i], q2 = qkvg[base + 64 + i];
    qkvg[base + i]      = (q1 * c - q2 * s) * sc;
    qkvg[base + 64 + i] = (q2 * c + q1 * s) * sc;
    size_t kb = base + 1024;
    float k1 = qkvg[kb + i], k2 = qkvg[kb + 64 + i];
    qkvg[kb + i]      = k1 * c - k2 * s;
    qkvg[kb + 64 + i] = k2 * c + k1 * s;
}

// ================= retention, 4 parallel phases (reading g_qkvg) ============
// index helpers: q col = h*128+dk ; k col = 1024 + h*128+dk ; v col = 2048 + h*256+ev

// Phase A: attn = (q@k^T)*M
#define ATTN_SMEM ((2 * 64 * 129 + 64) * 4)
__global__ __launch_bounds__(256) void ret_attn_kernel(const float* __restrict__ qkvg,
                                                       float* __restrict__ attn_out) {
    const int n = blockIdx.x, h = blockIdx.y, b = blockIdx.z;
    const int tid = threadIdx.x;
    extern __shared__ float sm[];
    float* qs   = sm;
    float* ks   = qs + 64 * 129;
    float* gpow = ks + 64 * 129;

    const float gamma = 1.0f - exp2f(-5.0f - (float)h);
    if (tid < 64) gpow[tid] = powf(gamma, (float)tid);

    const int t0 = n * CC;
    for (int e = tid; e < 64 * 128; e += 256) {
        int i = e >> 7, dk = e & 127;
        size_t gi = ((size_t)b * TT + t0 + i) * NQKVG + h * DKk + dk;
        qs[i * 129 + dk] = qkvg[gi];
        ks[i * 129 + dk] = qkvg[gi + 1024];
    }
    __syncthreads();

    const int ti = tid >> 4, te = tid & 15;
    float acc[4][4];
#pragma unroll
    for (int a = 0; a < 4; a++)
#pragma unroll
        for (int bq = 0; bq < 4; bq++) acc[a][bq] = 0.f;
    for (int dk = 0; dk < 128; dk++) {
        float ra[4], rb[4];
#pragma unroll
        for (int ii = 0; ii < 4; ii++) ra[ii] = qs[(ti * 4 + ii) * 129 + dk];
#pragma unroll
        for (int jj = 0; jj < 4; jj++) rb[jj] = ks[(te * 4 + jj) * 129 + dk];
#pragma unroll
        for (int ii = 0; ii < 4; ii++)
#pragma unroll
            for (int jj = 0; jj < 4; jj++) acc[ii][jj] += ra[ii] * rb[jj];
    }

    float* dst = attn_out + ((((size_t)b * HH + h) * NCHUNK + n) << 12);
#pragma unroll
    for (int ii = 0; ii < 4; ii++) {
        int i = ti * 4 + ii;
        float4 w;
        float* wp = &w.x;
#pragma unroll
        for (int jj = 0; jj < 4; jj++) {
            int j = te * 4 + jj;
            wp[jj] = (i >= j) ? acc[ii][jj] * gpow[i - j] : 0.f;
        }
        *(float4*)(dst + i * 64 + te * 4) = w;
    }
}

// Phase B: kv = (k*deck)^T @ v   (per DV slice of 64)
#define KV_SMEM ((64 * 129 + 64 * 65 + 64) * 4)
__global__ __launch_bounds__(256) void ret_kv_kernel(const float* __restrict__ qkvg,
                                                     float* __restrict__ kv_out) {
    const int sl = blockIdx.x & 3, n = blockIdx.x >> 2;
    const int h = blockIdx.y, b = blockIdx.z;
    const int tid = threadIdx.x;
    extern __shared__ float sm[];
    float* ks   = sm;
    float* vs   = ks + 64 * 129;
    float* deck = vs + 64 * 65;

    const float gamma = 1.0f - exp2f(-5.0f - (float)h);
    if (tid < 64) deck[tid] = powf(gamma, (float)(63 - tid));
    __syncthreads();

    const int t0 = n * CC;
    for (int e = tid; e < 64 * 128; e += 256) {
        int i = e >> 7, dk = e & 127;
        ks[i * 129 + dk] = qkvg[((size_t)b * TT + t0 + i) * NQKVG + 1024 + h * DKk + dk];
    }
    for (int e = tid; e < 64 * 64; e += 256) {
        int i = e >> 6, ev = e & 63;
        size_t gi = ((size_t)b * TT + t0 + i) * NQKVG + 2048 + h * DVv + sl * 64 + ev;
        vs[i * 65 + ev] = qkvg[gi] * deck[i];
    }
    __syncthreads();

    const int ti = tid >> 4, te = tid & 15;
    float acc[8][4];
#pragma unroll
    for (int a = 0; a < 8; a++)
#pragma unroll
        for (int bq = 0; bq < 4; bq++) acc[a][bq] = 0.f;
    for (int j = 0; j < 64; j++) {
        float ra[8], rb[4];
#pragma unroll
        for (int dd = 0; dd < 8; dd++) ra[dd] = ks[j * 129 + ti * 8 + dd];
#pragma unroll
        for (int ee = 0; ee < 4; ee++) rb[ee] = vs[j * 65 + te * 4 + ee];
#pragma unroll
        for (int dd = 0; dd < 8; dd++)
#pragma unroll
            for (int ee = 0; ee < 4; ee++) acc[dd][ee] += ra[dd] * rb[ee];
    }

    float* dst = kv_out + ((((size_t)b * HH + h) * NCHUNK + n) * DKk) * DVv + sl * 64;
#pragma unroll
    for (int dd = 0; dd < 8; dd++) {
        int dk = ti * 8 + dd;
        *(float4*)(dst + (size_t)dk * DVv + te * 4) =
            make_float4(acc[dd][0], acc[dd][1], acc[dd][2], acc[dd][3]);
    }
}

// Phase C: prefix scan of kv -> Spre
__global__ __launch_bounds__(256) void ret_scan_kernel(const float* __restrict__ kv,
                                                       float* __restrict__ Spre) {
    const int idx = blockIdx.x * 256 + threadIdx.x;
    const int bh  = idx >> 15;
    const int pos = idx & 32767;
    const int h   = bh & (HH - 1);
    const float gamma = 1.0f - exp2f(-5.0f - (float)h);
    const float gC = powf(gamma, 64.0f);

    const size_t base = (size_t)bh * NCHUNK * 32768 + pos;
    float s = 0.f;
    Spre[base] = 0.f;
    for (int n = 1; n < NCHUNK; n++) {
        s = gC * s + kv[base + (size_t)(n - 1) * 32768];
        Spre[base + (size_t)n * 32768] = s;
    }
}

// Phase D: o = attn @ v + decq * (q @ S_pre)   (per DV slice of 64)
#define OUT_SMEM ((64 * 65 + 64 * 65 + 64 * 129 + 128 * 65 + 64) * 4)
__global__ __launch_bounds__(256) void ret_out_kernel(const float* __restrict__ qkvg,
                                                      const float* __restrict__ attn,
                                                      const float* __restrict__ Spre,
                                                      float* __restrict__ o) {
    const int sl = blockIdx.x & 3, n = blockIdx.x >> 2;
    const int h = blockIdx.y, b = blockIdx.z;
    const int tid = threadIdx.x;
    extern __shared__ float sm[];
    float* at   = sm;
    float* vs   = at + 64 * 65;
    float* qs   = vs + 64 * 65;
    float* Ss   = qs + 64 * 129;
    float* decq = Ss + 128 * 65;

    const float gamma = 1.0f - exp2f(-5.0f - (float)h);
    if (tid < 64) decq[tid] = powf(gamma, (float)(tid + 1));

    const int t0 = n * CC;
    const size_t bh = (size_t)b * HH + h;
    const float* asrc = attn + ((bh * NCHUNK + n) << 12);
    for (int e = tid; e < 64 * 64; e += 256) {
        int i = e >> 6, j = e & 63;
        at[i * 65 + j] = asrc[e];
        vs[i * 65 + j] = qkvg[((size_t)b * TT + t0 + i) * NQKVG + 2048 + h * DVv + sl * 64 + j];
    }
    for (int e = tid; e < 64 * 128; e += 256) {
        int i = e >> 7, dk = e & 127;
        qs[i * 129 + dk] = qkvg[((size_t)b * TT + t0 + i) * NQKVG + h * DKk + dk];
    }
    const float* ssrc = Spre + ((bh * NCHUNK + n) * DKk) * DVv + sl * 64;
    for (int e = tid; e < 128 * 64; e += 256) {
        int dk = e >> 6, ev = e & 63;
        Ss[dk * 65 + ev] = ssrc[(size_t)dk * DVv + ev];
    }
    __syncthreads();

    const int ti = tid >> 4, te = tid & 15;
    float aI[4][4], aS[4][4];
#pragma unroll
    for (int a = 0; a < 4; a++)
#pragma unroll
        for (int bq = 0; bq < 4; bq++) { aI[a][bq] = 0.f; aS[a][bq] = 0.f; }

    for (int j = 0; j < 64; j++) {
        float ra[4], rb[4];
#pragma unroll
        for (int ii = 0; ii < 4; ii++) ra[ii] = at[(ti * 4 + ii) * 65 + j];
#pragma unroll
        for (int ee = 0; ee < 4; ee++) rb[ee] = vs[j * 65 + te * 4 + ee];
#pragma unroll
        for (int ii = 0; ii < 4; ii++)
#pragma unroll
            for (int ee = 0; ee < 4; ee++) aI[ii][ee] += ra[ii] * rb[ee];
    }
    for (int dk = 0; dk < 128; dk++) {
        float ra[4], rb[4];
#pragma unroll
        for (int ii = 0; ii < 4; ii++) ra[ii] = qs[(ti * 4 + ii) * 129 + dk];
#pragma unroll
        for (int ee = 0; ee < 4; ee++) rb[ee] = Ss[dk * 65 + te * 4 + ee];
#pragma unroll
        for (int ii = 0; ii < 4; ii++)
#pragma unroll
            for (int ee = 0; ee < 4; ee++) aS[ii][ee] += ra[ii] * rb[ee];
    }

#pragma unroll
    for (int ii = 0; ii < 4; ii++) {
        int i = ti * 4 + ii;
        float dq = decq[i];
        size_t base = (((size_t)b * TT + t0 + i) * HH + h) * DVv + sl * 64 + te * 4;
        *(float4*)(&o[base]) = make_float4(aI[ii][0] + dq * aS[ii][0],
                                           aI[ii][1] + dq * aS[ii][1],
                                           aI[ii][2] + dq * aS[ii][2],
                                           aI[ii][3] + dq * aS[ii][3]);
    }
}

// ---------------- RMSNorm + swish gate + bf16 split (g from combined buf) ----
__global__ __launch_bounds__(256) void normgate_split_kernel(const float* __restrict__ o,
                                                             const float* __restrict__ qkvg,
                                                             const float* __restrict__ norm_w,
                                                             __nv_bfloat16* __restrict__ ohi,
                                                             __nv_bfloat16* __restrict__ olo) {
    int warp = (blockIdx.x * blockDim.x + threadIdx.x) >> 5;
    int lane = threadIdx.x & 31;
    if (warp >= MROWS * HH) return;
    size_t base  = (size_t)warp * DVv;
    size_t gbase = (size_t)(warp >> 3) * NQKVG + 4096 + (size_t)(warp & 7) * DVv;

    float vals[8];
    float ss = 0.f;
#pragma unroll
    for (int r = 0; r < 8; r++) {
        vals[r] = o[base + lane + 32 * r];
        ss += vals[r] * vals[r];
    }
#pragma unroll
    for (int off = 16; off; off >>= 1) ss += __shfl_xor_sync(0xFFFFFFFFu, ss, off);
    float inv = rsqrtf(ss * (1.0f / 256.0f) + 1e-5f);

#pragma unroll
    for (int r = 0; r < 8; r++) {
        int ev = lane + 32 * r;
        float gv = qkvg[gbase + ev];
        float sg = 1.f / (1.f + expf(-gv));
        float res = vals[r] * inv * norm_w[ev] * gv * sg;
        __nv_bfloat16 h = __float2bfloat16(res);
        ohi[base + ev] = h;
        olo[base + ev] = __float2bfloat16(res - __bfloat162float(h));
    }
}

// ---------------- launch ----------------
static void launch_gemm(const __nv_bfloat16* Ahi, const __nv_bfloat16* Alo,
                        const __nv_bfloat16* Bhi, const __nv_bfloat16* Blo,
                        float* C, int M, int N, int K) {
    gemm_split_mma<<<dim3(N / 128, M / 128), 128, GEMM_SMEM_BYTES>>>(Ahi, Alo, Bhi, Blo, C, M, N, K);
}

extern "C" void kernel_launch(void* const* d_in, const int* in_sizes, int n_in,
                              void* d_out, int out_size) {
    const float* x      = (const float*)d_in[0];
    const float* Wq     = (const float*)d_in[1];
    const float* Wk     = (const float*)d_in[2];
    const float* Wv     = (const float*)d_in[3];
    const float* Wg     = (const float*)d_in[4];
    const float* Wo     = (const float*)d_in[5];
    const float* norm_w = (const float*)d_in[6];
    float* out = (float*)d_out;

    float *qkvg, *o, *attn, *kv, *S;
    cudaGetSymbolAddress((void**)&qkvg, g_qkvg);
    cudaGetSymbolAddress((void**)&o, g_o);
    cudaGetSymbolAddress((void**)&attn, g_attn);
    cudaGetSymbolAddress((void**)&kv, g_kv);
    cudaGetSymbolAddress((void**)&S, g_S);
    __nv_bfloat16 *xhi, *xlo, *ohi, *olo, *wallh, *walll, *woh, *wol;
    cudaGetSymbolAddress((void**)&xhi, g_xhi);
    cudaGetSymbolAddress((void**)&xlo, g_xlo);
    cudaGetSymbolAddress((void**)&ohi, g_ohi);
    cudaGetSymbolAddress((void**)&olo, g_olo);
    cudaGetSymbolAddress((void**)&wallh, g_wall_hi);
    cudaGetSymbolAddress((void**)&walll, g_wall_lo);
    cudaGetSymbolAddress((void**)&woh, g_wo_hi);
    cudaGetSymbolAddress((void**)&wol, g_wo_lo);

    cudaFuncSetAttribute(gemm_split_mma, cudaFuncAttributeMaxDynamicSharedMemorySize, GEMM_SMEM_BYTES);
    cudaFuncSetAttribute(ret_attn_kernel, cudaFuncAttributeMaxDynamicSharedMemorySize, ATTN_SMEM);
    cudaFuncSetAttribute(ret_kv_kernel, cudaFuncAttributeMaxDynamicSharedMemorySize, KV_SMEM);
    cudaFuncSetAttribute(ret_out_kernel, cudaFuncAttributeMaxDynamicSharedMemorySize, OUT_SMEM);

    // split inputs + transpose-split weights
    {
        int n = MROWS * DD;
        split_kernel<<<(n + 255) / 256, 256>>>(x, xhi, xlo, n);
    }
    tsplit_qkvg_kernel<<<dim3(NQKVG / 32, DD / 32), 256>>>(Wq, Wk, Wv, Wg, wallh, walll);
    tsplit_kernel<<<dim3(DD / 32, 2 * DD / 32), 256>>>(Wo, woh, wol, 2 * DD, DD);

    // combined projection GEMM (q|k|v|g)
    launch_gemm(xhi, xlo, wallh, walll, qkvg, MROWS, NQKVG, DD);

    // rope + scale (on combined buffer)
    {
        int total = BB * TT * HH * (DKk / 2);
        rope_kernel<<<(total + 255) / 256, 256>>>(qkvg);
    }

    // retention: 4 parallel phases
    ret_attn_kernel<<<dim3(NCHUNK, HH, BB), 256, ATTN_SMEM>>>(qkvg, attn);
    ret_kv_kernel<<<dim3(4 * NCHUNK, HH, BB), 256, KV_SMEM>>>(qkvg, kv);
    ret_scan_kernel<<<(NBH * DKk * DVv) / 256, 256>>>(kv, S);
    ret_out_kernel<<<dim3(4 * NCHUNK, HH, BB), 256, OUT_SMEM>>>(qkvg, attn, S, o);

    // rmsnorm + gate + split (fused)
    {
        int warps = MROWS * HH;
        normgate_split_kernel<<<(warps * 32 + 255) / 256, 256>>>(o, qkvg, norm_w, ohi, olo);
    }

    // output projection on tensor cores
    launch_gemm(ohi, olo, woh, wol, out, MROWS, DD, 2 * DD);
}